// round 2
// baseline (speedup 1.0000x reference)
#include <cuda_runtime.h>
#include <math.h>

// ---------------- problem dims ----------------
#define Bt 1024
#define St 64
#define Ct 256
#define Ht 8
#define FFt 1024
#define Nn 100000
#define Ee 400000
#define Ff 128
#define EPSf 1e-5f
#define ROWS_TAB (Bt*St)            // 65536
#define TAB_OUT_ELEMS (ROWS_TAB*Ct) // 16777216
#define GNN_OUT_ELEMS (Nn*Ff)       // 12800000

#define CDIV(a,b) (((a)+(b)-1)/(b))

// ---------------- scratch (static device allocations) ----------------
__device__ float g_qkv[(size_t)ROWS_TAB*768];    // qkv, then out_proj result
__device__ float g_big[(size_t)ROWS_TAB*1024];   // ffn1, then edge h [E,128]
__device__ float g_tmp2[(size_t)ROWS_TAB*256];   // attn o, ffn2, post out
__device__ float g_h1[(size_t)ROWS_TAB*256];     // h1, then linp out
__device__ float g_mean[(size_t)Nn*Ff];
__device__ float g_std [(size_t)Nn*Ff];
__device__ float g_mx  [(size_t)Nn*Ff];
__device__ float g_mn  [(size_t)Nn*Ff];
__device__ float g_amp[Nn], g_att[Nn];
__device__ int   g_deg[Nn];
__device__ int   g_rowstart[Nn+1];
__device__ int   g_cursor[Nn];
__device__ int   g_eid[Ee];
__device__ float g_w3p[Ff*Ff];
__device__ float g_bp[Ff];
__device__ float g_bnsum[Ff], g_bnsq[Ff];

// ---------------- generic SGEMM: C[M,N] = A[M,K] @ W[N,K]^T + bias, opt relu ----------------
// block tile 128x128, K-step 8, 256 threads, 8x8 per thread
__global__ __launch_bounds__(256) void k_sgemm(
    const float* __restrict__ A, const float* __restrict__ W,
    const float* __restrict__ bias, float* __restrict__ C,
    int M, int N, int K, int relu)
{
    __shared__ float As[8][128];
    __shared__ float Ws[8][128];
    int tid = threadIdx.x;
    int bm = blockIdx.y, bn = blockIdx.x;
    int row = tid >> 1;
    int kq  = (tid & 1) * 4;
    int grow = bm*128 + row;        // A row
    int gcol = bn*128 + row;        // W row (output channel)
    const float* Arow = A + (size_t)grow * K;
    const float* Wrow = W + (size_t)gcol * K;
    int ty = tid >> 4, tx = tid & 15;

    float acc[8][8];
    #pragma unroll
    for (int i=0;i<8;i++)
        #pragma unroll
        for (int j=0;j<8;j++) acc[i][j]=0.f;

    for (int k0=0; k0<K; k0+=8) {
        float4 av = make_float4(0,0,0,0);
        if (grow < M) av = *(const float4*)(Arow + k0 + kq);
        float4 wv = *(const float4*)(Wrow + k0 + kq);
        As[kq+0][row]=av.x; As[kq+1][row]=av.y; As[kq+2][row]=av.z; As[kq+3][row]=av.w;
        Ws[kq+0][row]=wv.x; Ws[kq+1][row]=wv.y; Ws[kq+2][row]=wv.z; Ws[kq+3][row]=wv.w;
        __syncthreads();
        #pragma unroll
        for (int k=0;k<8;k++){
            float4 a0 = *(const float4*)&As[k][ty*8];
            float4 a1 = *(const float4*)&As[k][ty*8+4];
            float4 b0 = *(const float4*)&Ws[k][tx*8];
            float4 b1 = *(const float4*)&Ws[k][tx*8+4];
            float a[8]={a0.x,a0.y,a0.z,a0.w,a1.x,a1.y,a1.z,a1.w};
            float b[8]={b0.x,b0.y,b0.z,b0.w,b1.x,b1.y,b1.z,b1.w};
            #pragma unroll
            for (int i=0;i<8;i++)
                #pragma unroll
                for (int j=0;j<8;j++) acc[i][j] += a[i]*b[j];
        }
        __syncthreads();
    }

    int m0 = bm*128 + ty*8, n0 = bn*128 + tx*8;
    #pragma unroll
    for (int i=0;i<8;i++){
        if (m0+i < M){
            float out[8];
            #pragma unroll
            for (int j=0;j<8;j++){
                float v = acc[i][j] + bias[n0+j];
                out[j] = relu ? fmaxf(v,0.f) : v;
            }
            float* cp = C + (size_t)(m0+i)*N + n0;
            *(float4*)cp     = make_float4(out[0],out[1],out[2],out[3]);
            *(float4*)(cp+4) = make_float4(out[4],out[5],out[6],out[7]);
        }
    }
}

// ---------------- attention: one block per (b,h), S=64, dh=32 ----------------
__global__ __launch_bounds__(256) void k_attn(const float* __restrict__ qkv, float* __restrict__ O)
{
    __shared__ float qs[64*33], ks[64*33], vs[64*33];
    __shared__ float ss[64*65];
    int bh = blockIdx.x;
    int b = bh >> 3, h = bh & 7;
    int tid = threadIdx.x;
    size_t base = (size_t)b*64*768 + h*32;

    for (int idx=tid; idx<2048; idx+=256){
        int s=idx>>5, d=idx&31;
        size_t g = base + (size_t)s*768 + d;
        qs[s*33+d]=qkv[g]; ks[s*33+d]=qkv[g+256]; vs[s*33+d]=qkv[g+512];
    }
    __syncthreads();

    const float scale = 0.17677669529663687f; // 1/sqrt(32)
    for (int idx=tid; idx<4096; idx+=256){
        int i=idx>>6, j=idx&63;
        float s=0.f;
        #pragma unroll
        for (int d=0;d<32;d++) s += qs[i*33+d]*ks[j*33+d];
        ss[i*65+j]=s*scale;
    }
    __syncthreads();

    int w=tid>>5, l=tid&31;
    for (int r=w; r<64; r+=8){
        float v0=ss[r*65+l], v1=ss[r*65+32+l];
        float mx=fmaxf(v0,v1);
        #pragma unroll
        for (int o=16;o;o>>=1) mx=fmaxf(mx,__shfl_xor_sync(0xffffffffu,mx,o));
        float e0=__expf(v0-mx), e1=__expf(v1-mx);
        float sm=e0+e1;
        #pragma unroll
        for (int o=16;o;o>>=1) sm+=__shfl_xor_sync(0xffffffffu,sm,o);
        float inv=1.f/sm;
        ss[r*65+l]=e0*inv; ss[r*65+32+l]=e1*inv;
    }
    __syncthreads();

    for (int idx=tid; idx<2048; idx+=256){
        int i=idx>>5, d=idx&31;
        float s=0.f;
        #pragma unroll
        for (int j=0;j<64;j++) s += ss[i*65+j]*vs[j*33+d];
        O[(size_t)(b*64+i)*256 + h*32 + d]=s;
    }
}

// ---------------- block reduction helper (256 threads) ----------------
__device__ __forceinline__ float blk_sum(float v){
    __shared__ float sh[8];
    int l=threadIdx.x&31, w=threadIdx.x>>5;
    #pragma unroll
    for (int o=16;o;o>>=1) v += __shfl_xor_sync(0xffffffffu,v,o);
    if (l==0) sh[w]=v;
    __syncthreads();
    if (w==0){
        float r = (l<8)? sh[l] : 0.f;
        #pragma unroll
        for (int o=16;o;o>>=1) r += __shfl_xor_sync(0xffffffffu,r,o);
        if (l==0) sh[0]=r;
    }
    __syncthreads();
    float r = sh[0];
    __syncthreads();
    return r;
}

// h1 = LN(x + a)
__global__ __launch_bounds__(256) void k_ln1(
    const float* __restrict__ x, const float* __restrict__ a,
    const float* __restrict__ g, const float* __restrict__ bta,
    float* __restrict__ out)
{
    int r=blockIdx.x, c=threadIdx.x;
    size_t i=(size_t)r*256+c;
    float t = x[i]+a[i];
    float mu = blk_sum(t)*(1.f/256.f);
    float d = t-mu;
    float var = blk_sum(d*d)*(1.f/256.f);
    out[i] = g[c]*d*rsqrtf(var+EPSf)+bta[c];
}

// out = LN2(LN1(h1+f2))  (ln2 then tab_norm)
__global__ __launch_bounds__(256) void k_ln2double(
    const float* __restrict__ h1, const float* __restrict__ f2,
    const float* __restrict__ g2, const float* __restrict__ b2,
    const float* __restrict__ tg, const float* __restrict__ tb,
    float* __restrict__ out)
{
    int r=blockIdx.x, c=threadIdx.x;
    size_t i=(size_t)r*256+c;
    float t = h1[i]+f2[i];
    float mu1 = blk_sum(t)*(1.f/256.f);
    float d1 = t-mu1;
    float v1 = blk_sum(d1*d1)*(1.f/256.f);
    float h2 = g2[c]*d1*rsqrtf(v1+EPSf)+b2[c];
    float mu2 = blk_sum(h2)*(1.f/256.f);
    float d2 = h2-mu2;
    float v2 = blk_sum(d2*d2)*(1.f/256.f);
    out[i] = tg[c]*d2*rsqrtf(v2+EPSf)+tb[c];
}

// ---------------- GNN prep: W3' = W3 @ enc_w ; b' = pre_b + W3 @ enc_b ----------------
__global__ void k_prep(const float* __restrict__ pre_w, const float* __restrict__ pre_b,
                       const float* __restrict__ enc_w, const float* __restrict__ enc_b)
{
    int i = blockIdx.x;   // output row 0..127
    int k = threadIdx.x;  // col 0..127
    float s=0.f;
    for (int j=0;j<128;j++) s += pre_w[i*384+256+j]*enc_w[j*128+k];
    g_w3p[i*128+k]=s;
    if (k==0){
        float t = pre_b[i];
        for (int j=0;j<128;j++) t += pre_w[i*384+256+j]*enc_b[j];
        g_bp[i]=t;
    }
}

__global__ void k_deg(const int* __restrict__ ei){
    int e = blockIdx.x*blockDim.x + threadIdx.x;
    if (e < Ee) atomicAdd(&g_deg[ei[Ee + e]], 1);
}

// exclusive scan of g_deg into g_rowstart (single block, 1024 threads)
__global__ __launch_bounds__(1024) void k_scan(){
    __shared__ int part[1024];
    int tid=threadIdx.x;
    const int chunk=(Nn+1023)/1024;
    int beg=tid*chunk;
    int end=min(beg+chunk, Nn);
    int s=0;
    for (int i=beg;i<end;i++) s+=g_deg[i];
    part[tid]=s;
    __syncthreads();
    for (int d=1; d<1024; d<<=1){
        int v=part[tid];
        if (tid>=d) v+=part[tid-d];
        __syncthreads();
        part[tid]=v;
        __syncthreads();
    }
    int off = (tid==0)?0:part[tid-1];
    for (int i=beg;i<end;i++){ g_rowstart[i]=off; off+=g_deg[i]; }
    if (end==Nn) g_rowstart[Nn]=off;
}

__global__ void k_scatter(const int* __restrict__ ei){
    int e = blockIdx.x*blockDim.x + threadIdx.x;
    if (e < Ee){
        int d = ei[Ee + e];
        int pos = atomicAdd(&g_cursor[d],1);
        g_eid[g_rowstart[d]+pos] = e;
    }
}

// ---------------- edge pre GEMM: h[e] = x[dst]@W1^T + x[src]@W2^T + ea@W3'^T + b' ----------------
__global__ __launch_bounds__(256) void k_pre_gemm(
    const float* __restrict__ xg, const float* __restrict__ ea,
    const int* __restrict__ ei, const float* __restrict__ pre_w,
    float* __restrict__ H)
{
    __shared__ float As[8][128];
    __shared__ float Ws[8][128];
    __shared__ int sdst[128], ssrc[128];
    int tid=threadIdx.x, bm=blockIdx.x;
    int row=tid>>1, kq=(tid&1)*4;
    if (tid<128){
        int e = bm*128+tid;
        sdst[tid]=ei[Ee+e];
        ssrc[tid]=ei[e];
    }
    __syncthreads();
    int ty=tid>>4, tx=tid&15;
    float acc[8][8];
    #pragma unroll
    for (int i=0;i<8;i++)
        #pragma unroll
        for (int j=0;j<8;j++) acc[i][j]=0.f;

    for (int k0=0;k0<384;k0+=8){
        int c=k0+kq;
        float4 av, wv;
        if (k0<128)        av = *(const float4*)(xg + (size_t)sdst[row]*128 + c);
        else if (k0<256)   av = *(const float4*)(xg + (size_t)ssrc[row]*128 + (c-128));
        else               av = *(const float4*)(ea + (size_t)(bm*128+row)*128 + (c-256));
        if (k0<256) wv = *(const float4*)(pre_w + (size_t)row*384 + c);
        else        wv = *(const float4*)(g_w3p + (size_t)row*128 + (c-256));
        As[kq+0][row]=av.x; As[kq+1][row]=av.y; As[kq+2][row]=av.z; As[kq+3][row]=av.w;
        Ws[kq+0][row]=wv.x; Ws[kq+1][row]=wv.y; Ws[kq+2][row]=wv.z; Ws[kq+3][row]=wv.w;
        __syncthreads();
        #pragma unroll
        for (int k=0;k<8;k++){
            float4 a0=*(const float4*)&As[k][ty*8], a1=*(const float4*)&As[k][ty*8+4];
            float4 b0=*(const float4*)&Ws[k][tx*8], b1=*(const float4*)&Ws[k][tx*8+4];
            float a[8]={a0.x,a0.y,a0.z,a0.w,a1.x,a1.y,a1.z,a1.w};
            float b[8]={b0.x,b0.y,b0.z,b0.w,b1.x,b1.y,b1.z,b1.w};
            #pragma unroll
            for (int i=0;i<8;i++)
                #pragma unroll
                for (int j=0;j<8;j++) acc[i][j]+=a[i]*b[j];
        }
        __syncthreads();
    }
    int m0=bm*128+ty*8, n0=tx*8;
    #pragma unroll
    for (int i=0;i<8;i++){
        float* cp = H + (size_t)(m0+i)*128 + n0;
        float out[8];
        #pragma unroll
        for (int j=0;j<8;j++) out[j]=acc[i][j]+g_bp[n0+j];
        *(float4*)cp     = make_float4(out[0],out[1],out[2],out[3]);
        *(float4*)(cp+4) = make_float4(out[4],out[5],out[6],out[7]);
    }
}

// ---------------- per-node aggregation (CSR, deterministic, no atomics) ----------------
__global__ __launch_bounds__(128) void k_agg(const float* __restrict__ H, float delta){
    int n = blockIdx.x;
    int c = threadIdx.x;
    int s=g_rowstart[n], e=g_rowstart[n+1];
    float sum=0.f, sq=0.f, mx=-3.402823466e38f, mn=3.402823466e38f;
    for (int j=s;j<e;j++){
        float v = H[(size_t)g_eid[j]*128 + c];
        sum+=v; sq+=v*v; mx=fmaxf(mx,v); mn=fminf(mn,v);
    }
    float cnt=(float)(e-s);
    float denom=fmaxf(cnt,1.f);
    float mean=sum/denom;
    float m2=sq/denom;
    float sd=sqrtf(fmaxf(m2-mean*mean,0.f)+EPSf);
    size_t o=(size_t)n*128+c;
    g_mean[o]=mean;
    g_std[o]=sd;
    g_mx[o]=(cnt>0.f)?mx:0.f;
    g_mn[o]=(cnt>0.f)?mn:0.f;
    if (c==0){
        float degc=fmaxf(cnt,1.f);
        float lg=logf(degc+1.f);
        g_amp[n]=lg/delta;
        g_att[n]=delta/lg;
    }
}

// ---------------- post GEMM with synthesized A (K=1664) ----------------
__global__ __launch_bounds__(256) void k_post_gemm(
    const float* __restrict__ xg, const float* __restrict__ post_w,
    const float* __restrict__ post_b, float* __restrict__ C)
{
    __shared__ float As[8][128];
    __shared__ float Ws[8][128];
    __shared__ float samp[128], satt[128];
    int tid=threadIdx.x, bm=blockIdx.x;
    int row=tid>>1, kq=(tid&1)*4;
    if (tid<128){
        int n=bm*128+tid;
        bool ok = n<Nn;
        samp[tid]= ok? g_amp[n]:0.f;
        satt[tid]= ok? g_att[n]:0.f;
    }
    __syncthreads();
    int ty=tid>>4, tx=tid&15;
    int grow=bm*128+row;
    bool okr = grow<Nn;
    float acc[8][8];
    #pragma unroll
    for (int i=0;i<8;i++)
        #pragma unroll
        for (int j=0;j<8;j++) acc[i][j]=0.f;

    for (int k0=0;k0<1664;k0+=8){
        float4 av = make_float4(0,0,0,0);
        if (okr){
            if (k0<128){
                av = *(const float4*)(xg + (size_t)grow*128 + k0+kq);
            } else {
                int kk=k0-128;
                int grp=kk>>9;            // 0:agg 1:agg*amp 2:agg*att
                int within=kk&511;
                int which=within>>7;      // 0:mean 1:mx 2:mn 3:std
                int cc=(within&127)+kq;
                const float* buf = (which==0)? g_mean : (which==1)? g_mx : (which==2)? g_mn : g_std;
                av = *(const float4*)(buf + (size_t)grow*128 + cc);
                float sc = (grp==0)?1.f : (grp==1)? samp[row] : satt[row];
                av.x*=sc; av.y*=sc; av.z*=sc; av.w*=sc;
            }
        }
        float4 wv = *(const float4*)(post_w + (size_t)row*1664 + k0+kq);
        As[kq+0][row]=av.x; As[kq+1][row]=av.y; As[kq+2][row]=av.z; As[kq+3][row]=av.w;
        Ws[kq+0][row]=wv.x; Ws[kq+1][row]=wv.y; Ws[kq+2][row]=wv.z; Ws[kq+3][row]=wv.w;
        __syncthreads();
        #pragma unroll
        for (int k=0;k<8;k++){
            float4 a0=*(const float4*)&As[k][ty*8], a1=*(const float4*)&As[k][ty*8+4];
            float4 b0=*(const float4*)&Ws[k][tx*8], b1=*(const float4*)&Ws[k][tx*8+4];
            float a[8]={a0.x,a0.y,a0.z,a0.w,a1.x,a1.y,a1.z,a1.w};
            float b[8]={b0.x,b0.y,b0.z,b0.w,b1.x,b1.y,b1.z,b1.w};
            #pragma unroll
            for (int i=0;i<8;i++)
                #pragma unroll
                for (int j=0;j<8;j++) acc[i][j]+=a[i]*b[j];
        }
        __syncthreads();
    }
    int m0=bm*128+ty*8, n0=tx*8;
    #pragma unroll
    for (int i=0;i<8;i++){
        if (m0+i<Nn){
            float out[8];
            #pragma unroll
            for (int j=0;j<8;j++) out[j]=acc[i][j]+post_b[n0+j];
            float* cp = C + (size_t)(m0+i)*128 + n0;
            *(float4*)cp     = make_float4(out[0],out[1],out[2],out[3]);
            *(float4*)(cp+4) = make_float4(out[4],out[5],out[6],out[7]);
        }
    }
}

// ---------------- BatchNorm stats ----------------
__global__ __launch_bounds__(128) void k_bnstats(const float* __restrict__ Y){
    int c=threadIdx.x;
    float s=0.f, q=0.f;
    for (int r=blockIdx.x; r<Nn; r+=gridDim.x){
        float v=Y[(size_t)r*128+c];
        s+=v; q+=v*v;
    }
    atomicAdd(&g_bnsum[c], s);
    atomicAdd(&g_bnsq[c], q);
}

// ---------------- GNN final: BN + relu + residual avg ----------------
__global__ void k_gnn_final(const float* __restrict__ Y, const float* __restrict__ xg,
                            const float* __restrict__ bg, const float* __restrict__ bb,
                            float* __restrict__ out)
{
    int i = blockIdx.x*blockDim.x + threadIdx.x;
    if (i < Nn*Ff){
        int c = i & 127;
        float mu = g_bnsum[c]*(1.f/Nn);
        float var = g_bnsq[c]*(1.f/Nn) - mu*mu;
        float y = bg[c]*(Y[i]-mu)*rsqrtf(var+EPSf)+bb[c];
        out[i] = (xg[i] + fmaxf(y,0.f))*0.5f;
    }
}

__global__ void k_copy4(const float4* __restrict__ s, float4* __restrict__ d, int n){
    for (int i = blockIdx.x*blockDim.x + threadIdx.x; i < n; i += gridDim.x*blockDim.x)
        d[i]=s[i];
}

// ---------------- launch ----------------
extern "C" void kernel_launch(void* const* d_in, const int* in_sizes, int n_in,
                              void* d_out, int out_size)
{
    const float* x_tab      = (const float*)d_in[0];
    const float* x_gnn      = (const float*)d_in[1];
    const int*   edge_index = (const int*)  d_in[2];
    const float* edge_attr  = (const float*)d_in[3];
    const float* in_proj_w  = (const float*)d_in[4];
    const float* in_proj_b  = (const float*)d_in[5];
    const float* out_proj_w = (const float*)d_in[6];
    const float* out_proj_b = (const float*)d_in[7];
    const float* lin1_w     = (const float*)d_in[8];
    const float* lin1_b     = (const float*)d_in[9];
    const float* lin2_w     = (const float*)d_in[10];
    const float* lin2_b     = (const float*)d_in[11];
    const float* ln1_g      = (const float*)d_in[12];
    const float* ln1_b      = (const float*)d_in[13];
    const float* ln2_g      = (const float*)d_in[14];
    const float* ln2_b      = (const float*)d_in[15];
    const float* tabn_g     = (const float*)d_in[16];
    const float* tabn_b     = (const float*)d_in[17];
    const float* enc_w      = (const float*)d_in[18];
    const float* enc_b      = (const float*)d_in[19];
    const float* pre_w      = (const float*)d_in[20];
    const float* pre_b      = (const float*)d_in[21];
    const float* post_w     = (const float*)d_in[22];
    const float* post_b     = (const float*)d_in[23];
    const float* linp_w     = (const float*)d_in[24];
    const float* linp_b     = (const float*)d_in[25];
    const float* bn_g       = (const float*)d_in[26];
    const float* bn_b       = (const float*)d_in[27];

    float *qkv,*big,*tmp2,*h1;
    int *deg,*cursor;
    float *bnsum,*bnsq;
    cudaGetSymbolAddress((void**)&qkv,  g_qkv);
    cudaGetSymbolAddress((void**)&big,  g_big);
    cudaGetSymbolAddress((void**)&tmp2, g_tmp2);
    cudaGetSymbolAddress((void**)&h1,   g_h1);
    cudaGetSymbolAddress((void**)&deg,    g_deg);
    cudaGetSymbolAddress((void**)&cursor, g_cursor);
    cudaGetSymbolAddress((void**)&bnsum,  g_bnsum);
    cudaGetSymbolAddress((void**)&bnsq,   g_bnsq);

    float* out_tab = (float*)d_out;
    float* out_gnn = (float*)d_out + TAB_OUT_ELEMS;
    float* out_ea  = (float*)d_out + TAB_OUT_ELEMS + GNN_OUT_ELEMS;

    // PNA delta (avg_deg log)
    const double dh[5]={0.0,20000.0,30000.0,30000.0,20000.0};
    double sacc=0.0, tacc=0.0;
    for (int i=0;i<5;i++){ sacc += log((double)i+1.0)*dh[i]; tacc += dh[i]; }
    float delta = (float)(sacc/tacc);

    // -------- tab branch --------
    k_sgemm<<<dim3(6,512),256>>>(x_tab, in_proj_w, in_proj_b, qkv, ROWS_TAB,768,256,0);
    k_attn<<<Bt*Ht,256>>>(qkv, tmp2);
    k_sgemm<<<dim3(2,512),256>>>(tmp2, out_proj_w, out_proj_b, qkv, ROWS_TAB,256,256,0);
    k_ln1<<<ROWS_TAB,256>>>(x_tab, qkv, ln1_g, ln1_b, h1);
    k_sgemm<<<dim3(8,512),256>>>(h1, lin1_w, lin1_b, big, ROWS_TAB,1024,256,1);
    k_sgemm<<<dim3(2,512),256>>>(big, lin2_w, lin2_b, tmp2, ROWS_TAB,256,1024,0);
    k_ln2double<<<ROWS_TAB,256>>>(h1, tmp2, ln2_g, ln2_b, tabn_g, tabn_b, out_tab);

    // -------- gnn branch --------
    k_prep<<<128,128>>>(pre_w, pre_b, enc_w, enc_b);
    cudaMemsetAsync(deg,    0, sizeof(int)*Nn);
    cudaMemsetAsync(cursor, 0, sizeof(int)*Nn);
    cudaMemsetAsync(bnsum,  0, sizeof(float)*Ff);
    cudaMemsetAsync(bnsq,   0, sizeof(float)*Ff);
    k_deg<<<CDIV(Ee,256),256>>>(edge_index);
    k_scan<<<1,1024>>>();
    k_scatter<<<CDIV(Ee,256),256>>>(edge_index);
    k_pre_gemm<<<Ee/128,256>>>(x_gnn, edge_attr, edge_index, pre_w, big);
    k_agg<<<Nn,128>>>(big, delta);
    k_post_gemm<<<CDIV(Nn,128),256>>>(x_gnn, post_w, post_b, tmp2);
    k_sgemm<<<dim3(1,CDIV(Nn,128)),256>>>(tmp2, linp_w, linp_b, h1, Nn,128,128,0);
    k_bnstats<<<512,128>>>(h1);
    k_gnn_final<<<CDIV(Nn*Ff,256),256>>>(h1, x_gnn, bn_g, bn_b, out_gnn);

    // -------- edge_attr passthrough --------
    k_copy4<<<2048,256>>>((const float4*)edge_attr, (float4*)out_ea, (Ee*Ff)/4);
}